// round 3
// baseline (speedup 1.0000x reference)
#include <cuda_runtime.h>
#include <math.h>
#include <stdint.h>

#define Bb 16
#define Cc 32
#define Hh 128
#define Ww 128
#define HW 16384
#define Rr 8
#define OUTC 32

typedef unsigned long long ull;

// ---------------- scratch (device globals; no allocation) ----------------
__device__ __align__(16) float d_kern[Bb * Rr * 288 * 32];   // [b][r][ckl][oo], ckl=c*9+kl
__device__ unsigned char  d_sel[Bb * HW];                    // r1 | r2<<3
__device__ int            d_segcnt[Bb * Rr * 64];
__device__ int            d_segbase[Bb * Rr * 64];
__device__ int            d_cnt[Bb * Rr];
__device__ unsigned short d_list[Bb * Rr * HW];              // pix | flags<<14 (sorted by pix)
__device__ __align__(16) float d_cat[(size_t)Bb * 64 * HW];  // CHANNEL-FIRST [b][ch][pix]
__device__ __align__(16) float d_wft[9 * 64 * 32];           // [kl][ch][o]

// ---------------- f32x2 helpers ----------------
__device__ __forceinline__ ull pack2(float v) {
    ull r; asm("mov.b64 %0, {%1, %1};" : "=l"(r) : "f"(v)); return r;
}
__device__ __forceinline__ ull ffma2(ull a, ull b, ull c) {
    ull d; asm("fma.rn.f32x2 %0, %1, %2, %3;" : "=l"(d) : "l"(a), "l"(b), "l"(c)); return d;
}

// ---------------- S1: argmax select + per-segment counts ----------------
__global__ void __launch_bounds__(256) s1_select_kernel(
    const float* __restrict__ guide,
    const float* __restrict__ w_spa, const float* __restrict__ b_spa,
    const float* __restrict__ w_spec, const float* __restrict__ b_spec) {
    int t = threadIdx.x, seg = blockIdx.x, b = blockIdx.y;
    int pix = seg * 256 + t;

    float gv[Cc];
    #pragma unroll
    for (int c = 0; c < Cc; c++)
        gv[c] = __ldg(guide + ((size_t)(b * Cc + c)) * HW + pix);

    float best1 = -1e30f, best2 = -1e30f;
    int r1 = 0, r2 = 0;
    for (int r = 0; r < Rr; r++) {
        float s1 = __ldg(b_spa + r), s2 = __ldg(b_spec + r);
        #pragma unroll
        for (int c = 0; c < Cc; c++) {
            s1 += gv[c] * __ldg(w_spa + r * Cc + c);
            s2 += gv[c] * __ldg(w_spec + r * Cc + c);
        }
        if (s1 > best1) { best1 = s1; r1 = r; }
        if (s2 > best2) { best2 = s2; r2 = r; }
    }
    d_sel[b * HW + pix] = (unsigned char)(r1 | (r2 << 3));

    __shared__ int scnt[Rr];
    if (t < Rr) scnt[t] = 0;
    __syncthreads();
    if (r1 == r2) atomicAdd(&scnt[r1], 1);
    else { atomicAdd(&scnt[r1], 1); atomicAdd(&scnt[r2], 1); }
    __syncthreads();
    if (t < Rr) d_segcnt[(b * Rr + t) * 64 + seg] = scnt[t];
}

// ---------------- S2: per-list exclusive scan over segments ----------------
__global__ void s2_scan_kernel() {
    int t = threadIdx.x;           // one thread per (b,r) list
    if (t >= Bb * Rr) return;
    int s = 0;
    for (int seg = 0; seg < 64; seg++) {
        d_segbase[t * 64 + seg] = s;
        s += d_segcnt[t * 64 + seg];
    }
    d_cnt[t] = s;
}

// ---------------- S3: emit sorted lists (ballot rank, deterministic) ----------------
__global__ void __launch_bounds__(256) s3_emit_kernel() {
    int t = threadIdx.x, seg = blockIdx.x, b = blockIdx.y;
    int w = t >> 5, lane = t & 31;
    int pix = seg * 256 + t;
    int sel = d_sel[b * HW + pix];
    int r1 = sel & 7, r2 = sel >> 3;

    __shared__ int wcnt[8][8];    // [warp][r]
    int rank1 = 0, rank2 = 0;
    unsigned ltm = (1u << lane) - 1u;
    #pragma unroll
    for (int r = 0; r < Rr; r++) {
        unsigned m = __ballot_sync(0xFFFFFFFFu, (r1 == r) || (r2 == r));
        if (lane == 0) wcnt[w][r] = __popc(m);
        if (r1 == r) rank1 = __popc(m & ltm);
        if (r2 == r) rank2 = __popc(m & ltm);
    }
    __syncthreads();
    int wb1 = 0, wb2 = 0;
    for (int w2 = 0; w2 < w; w2++) { wb1 += wcnt[w2][r1]; wb2 += wcnt[w2][r2]; }

    unsigned short pv = (unsigned short)pix;
    if (r1 == r2) {
        int off = d_segbase[(b * Rr + r1) * 64 + seg] + wb1 + rank1;
        d_list[(b * Rr + r1) * HW + off] = (unsigned short)(pv | (3u << 14));
    } else {
        int off1 = d_segbase[(b * Rr + r1) * 64 + seg] + wb1 + rank1;
        d_list[(b * Rr + r1) * HW + off1] = (unsigned short)(pv | (1u << 14));
        int off2 = d_segbase[(b * Rr + r2) * 64 + seg] + wb2 + rank2;
        d_list[(b * Rr + r2) * HW + off2] = (unsigned short)(pv | (2u << 14));
    }
}

// ---------------- PREP: pool + gate + dynamic kernels + wf transpose ----------------
__global__ void __launch_bounds__(256) prep_kernel(
    const float* __restrict__ in,
    const float* __restrict__ w1, const float* __restrict__ b1,
    const float* __restrict__ w2, const float* __restrict__ b2,
    const float* __restrict__ w_f) {
    int b = blockIdx.x, t = threadIdx.x;

    if (b == 0) {  // fusion-weight transpose [kl][ch][o]
        for (int idx = t; idx < 9 * 64 * 32; idx += 256) {
            int o = idx & 31, ch = (idx >> 5) & 63, kl = idx >> 11;
            d_wft[idx] = w_f[(o * 64 + ch) * 9 + kl];
        }
    }

    __shared__ float spart[288 * 8];
    __shared__ float sp[288];   // pooled [c][9]
    __shared__ float sg[576];   // gate   [rr][9]

    {   // adaptive avg pool 3x3 with torch (overlapping) bin edges
        int c = t >> 3, sub = t & 7;
        const float* img = in + ((size_t)b * Cc + c) * HW;
        float bins[9];
        #pragma unroll
        for (int k = 0; k < 9; k++) bins[k] = 0.f;
        for (int yy = sub * 16; yy < sub * 16 + 16; yy++) {
            const float* row = img + yy * Ww;
            float xs0 = 0.f, xs1 = 0.f, xs2 = 0.f;
            for (int xx = 0;  xx < 43;  xx++) xs0 += row[xx];
            for (int xx = 42; xx < 86;  xx++) xs1 += row[xx];
            for (int xx = 85; xx < 128; xx++) xs2 += row[xx];
            if (yy <= 42)             { bins[0] += xs0; bins[1] += xs1; bins[2] += xs2; }
            if (yy >= 42 && yy <= 85) { bins[3] += xs0; bins[4] += xs1; bins[5] += xs2; }
            if (yy >= 85)             { bins[6] += xs0; bins[7] += xs1; bins[8] += xs2; }
        }
        #pragma unroll
        for (int k = 0; k < 9; k++) spart[(c * 9 + k) * 8 + sub] = bins[k];
    }
    __syncthreads();
    // FIX (R2 bug): sp has 288 entries but only 256 threads — grid-stride it.
    for (int i = t; i < 288; i += 256) {
        float s = 0.f;
        #pragma unroll
        for (int j = 0; j < 8; j++) s += spart[i * 8 + j];
        const int span[3] = {43, 44, 43};
        int k = i % 9;
        sp[i] = s / (float)(span[k / 3] * span[k % 3]);
    }
    __syncthreads();
    for (int idx = t; idx < 576; idx += 256) {   // gate
        int rr = idx / 9, kl = idx % 9;
        float s = __ldg(b1 + rr);
        #pragma unroll
        for (int c = 0; c < Cc; c++) s += sp[c * 9 + kl] * __ldg(w1 + rr * Cc + c);
        sg[idx] = 1.f / (1.f + expf(-s));
    }
    __syncthreads();
    for (int idx = t; idx < 73728; idx += 256) { // dynamic kernels
        int oo = idx & 31;
        int ckl = (idx >> 5) % 288;
        int r = idx / (288 * 32);
        int c = ckl / 9, kl = ckl % 9;
        int jj = r * 1024 + oo * 32 + c;
        float v = __ldg(b2 + jj);
        #pragma unroll
        for (int i = 0; i < 8; i++) v += sg[(r * 8 + i) * 9 + kl] * __ldg(w2 + jj * 8 + i);
        d_kern[(size_t)b * 73728 + idx] = v;
    }
}

// ---------------- dynconv: sorted-list selected-region conv ----------------
// grid (128, 8, 16), block 256. warp = 16 entries (2 streams x 8 lanes) x 32 oo.
__global__ void __launch_bounds__(256) dynconv_kernel(const float* __restrict__ in) {
    int b = blockIdx.z, r = blockIdx.y;
    int cnt = d_cnt[b * Rr + r];
    int base = blockIdx.x * 128;
    if (base >= cnt) return;

    __shared__ __align__(16) float ks[288 * 32];
    {
        const float4* kg = (const float4*)(d_kern + (size_t)(b * Rr + r) * 9216);
        float4* kd = (float4*)ks;
        for (int i = threadIdx.x; i < 2304; i += 256) kd[i] = kg[i];
    }
    __syncthreads();

    int w = threadIdx.x >> 5, lane = threadIdx.x & 31;
    int p = lane & 7, g = lane >> 3;
    const unsigned short* lst = d_list + (b * Rr + r) * HW;
    const float* inb = in + (size_t)b * Cc * HW;

    int e0 = base + w * 16 + p;
    int e1 = e0 + 8;
    int ent0 = (e0 < cnt) ? (int)lst[e0] : -1;
    int ent1 = (e1 < cnt) ? (int)lst[e1] : -1;
    int f0 = (ent0 >= 0) ? (ent0 >> 14) : 0;
    int f1 = (ent1 >= 0) ? (ent1 >> 14) : 0;
    int pix0 = ent0 & 0x3FFF, pix1 = ent1 & 0x3FFF;
    int y0 = pix0 >> 7, x0 = pix0 & 127;
    int y1 = pix1 >> 7, x1 = pix1 & 127;
    bool t0 = y0 > 0, bo0 = y0 < Hh - 1, l0 = x0 > 0, ri0 = x0 < Ww - 1;
    bool t1 = y1 > 0, bo1 = y1 < Hh - 1, l1 = x1 > 0, ri1 = x1 < Ww - 1;

    const float* p0 = inb + (long)(y0 - 1) * Ww + (x0 - 1);
    const float* p1 = inb + (long)(y1 - 1) * Ww + (x1 - 1);

    ull acc0[4] = {0, 0, 0, 0}, acc1[4] = {0, 0, 0, 0};

    for (int c = 0; c < Cc; c++, p0 += HW, p1 += HW) {
        const float* kc = ks + c * 288;   // c*9*32
        #pragma unroll
        for (int tap = 0; tap < 9; tap++) {
            const int ky = tap / 3, kx = tap % 3;
            bool rv0 = (ky == 0) ? t0 : ((ky == 2) ? bo0 : true);
            bool cv0 = (kx == 0) ? l0 : ((kx == 2) ? ri0 : true);
            bool rv1 = (ky == 0) ? t1 : ((ky == 2) ? bo1 : true);
            bool cv1 = (kx == 0) ? l1 : ((kx == 2) ? ri1 : true);
            float v0 = (rv0 && cv0) ? __ldg(p0 + ky * Ww + kx) : 0.f;
            float v1 = (rv1 && cv1) ? __ldg(p1 + ky * Ww + kx) : 0.f;
            ull a0 = pack2(v0), a1 = pack2(v1);
            const ulonglong2* kp = (const ulonglong2*)(kc + tap * 32 + g * 8);
            ulonglong2 ka = kp[0];
            ulonglong2 kb = kp[1];
            acc0[0] = ffma2(a0, ka.x, acc0[0]); acc0[1] = ffma2(a0, ka.y, acc0[1]);
            acc0[2] = ffma2(a0, kb.x, acc0[2]); acc0[3] = ffma2(a0, kb.y, acc0[3]);
            acc1[0] = ffma2(a1, ka.x, acc1[0]); acc1[1] = ffma2(a1, ka.y, acc1[1]);
            acc1[2] = ffma2(a1, kb.x, acc1[2]); acc1[3] = ffma2(a1, kb.y, acc1[3]);
        }
    }

    float* catb = d_cat + (size_t)b * 64 * HW;
    const float* a0f = (const float*)acc0;
    const float* a1f = (const float*)acc1;
    if (f0 & 1) {
        #pragma unroll
        for (int u = 0; u < 8; u++) catb[(g * 8 + u) * HW + pix0] = a0f[u];
    }
    if (f0 & 2) {
        #pragma unroll
        for (int u = 0; u < 8; u++) catb[(32 + g * 8 + u) * HW + pix0] = a0f[u];
    }
    if (f1 & 1) {
        #pragma unroll
        for (int u = 0; u < 8; u++) catb[(g * 8 + u) * HW + pix1] = a1f[u];
    }
    if (f1 & 2) {
        #pragma unroll
        for (int u = 0; u < 8; u++) catb[(32 + g * 8 + u) * HW + pix1] = a1f[u];
    }
}

// ---------------- fusion conv 3x3 (64->32) + bias + residual ----------------
// grid (4, 16, 16), block 256. warp = one row, 32 px (4 streams x 8 lanes) x 32 oo.
__global__ void __launch_bounds__(256) fusion_kernel(
    const float* __restrict__ in, const float* __restrict__ b_f,
    float* __restrict__ out) {
    int t = threadIdx.x, w = t >> 5, lane = t & 31;
    int p = lane & 7, g = lane >> 3;
    int b = blockIdx.z;
    int y = blockIdx.y * 8 + w;
    int xb = blockIdx.x * 32;

    const float* catb = d_cat + (size_t)b * 64 * HW;
    ull acc[4][4];
    #pragma unroll
    for (int j = 0; j < 4; j++)
        #pragma unroll
        for (int u = 0; u < 4; u++) acc[j][u] = 0;

    for (int ch = 0; ch < 64; ch++) {
        const float* chp = catb + (size_t)ch * HW;
        #pragma unroll
        for (int ky = 0; ky < 3; ky++) {
            int yy = y + ky - 1;
            bool rok = ((unsigned)yy < (unsigned)Hh);
            const float* rowp = chp + (long)yy * Ww;
            #pragma unroll
            for (int kx = 0; kx < 3; kx++) {
                const ulonglong2* wp =
                    (const ulonglong2*)(d_wft + (((ky * 3 + kx) * 64 + ch) * 32) + g * 8);
                ulonglong2 ka = __ldg(wp);
                ulonglong2 kb = __ldg(wp + 1);
                #pragma unroll
                for (int j = 0; j < 4; j++) {
                    int xx = xb + j * 8 + p + kx - 1;
                    bool ok = rok && ((unsigned)xx < (unsigned)Ww);
                    float v = ok ? __ldg(rowp + xx) : 0.f;
                    ull a = pack2(v);
                    acc[j][0] = ffma2(a, ka.x, acc[j][0]);
                    acc[j][1] = ffma2(a, ka.y, acc[j][1]);
                    acc[j][2] = ffma2(a, kb.x, acc[j][2]);
                    acc[j][3] = ffma2(a, kb.y, acc[j][3]);
                }
            }
        }
    }

    #pragma unroll
    for (int j = 0; j < 4; j++) {
        int x = xb + j * 8 + p;
        long pixo = (long)y * Ww + x;
        const float* af = (const float*)acc[j];
        #pragma unroll
        for (int u = 0; u < 8; u++) {
            int o = g * 8 + u;
            size_t idx = ((size_t)(b * OUTC + o)) * HW + pixo;
            out[idx] = af[u] + __ldg(b_f + o) + __ldg(in + idx);
        }
    }
}

// ---------------- launch ----------------
extern "C" void kernel_launch(void* const* d_in, const int* in_sizes, int n_in,
                              void* d_out, int out_size) {
    const float* input  = (const float*)d_in[0];
    const float* guide  = (const float*)d_in[1];
    const float* w1     = (const float*)d_in[2];
    const float* b1     = (const float*)d_in[3];
    const float* w2     = (const float*)d_in[4];
    const float* b2     = (const float*)d_in[5];
    const float* w_spa  = (const float*)d_in[6];
    const float* b_spa  = (const float*)d_in[7];
    const float* w_spec = (const float*)d_in[8];
    const float* b_spec = (const float*)d_in[9];
    const float* w_f    = (const float*)d_in[10];
    const float* b_f    = (const float*)d_in[11];
    float* out = (float*)d_out;

    s1_select_kernel<<<dim3(64, Bb), 256>>>(guide, w_spa, b_spa, w_spec, b_spec);
    s2_scan_kernel<<<1, 128>>>();
    s3_emit_kernel<<<dim3(64, Bb), 256>>>();
    prep_kernel<<<Bb, 256>>>(input, w1, b1, w2, b2, w_f);
    dynconv_kernel<<<dim3(128, Rr, Bb), 256>>>(input);
    fusion_kernel<<<dim3(4, 16, Bb), 256>>>(input, b_f, out);
}

// round 4
// speedup vs baseline: 1.5171x; 1.5171x over previous
#include <cuda_runtime.h>
#include <math.h>
#include <stdint.h>

#define Bb 16
#define Cc 32
#define Hh 128
#define Ww 128
#define HW 16384
#define Rr 8
#define OUTC 32

typedef unsigned long long ull;

// ---------------- scratch (device globals; no allocation) ----------------
__device__ __align__(16) float d_kern[Bb * Rr * 288 * 32];   // [b][r][ckl][oo], ckl=c*9+kl
__device__ float          d_pool[Bb * Cc * 9];               // [b][c][kl]
__device__ float          d_gate[Bb * 576];                  // [b][rr*9+kl]
__device__ unsigned char  d_sel[Bb * HW];                    // r1 | r2<<3
__device__ int            d_segcnt[Bb * Rr * 64];
__device__ int            d_segbase[Bb * Rr * 64];
__device__ int            d_cnt[Bb * Rr];
__device__ unsigned short d_list[Bb * Rr * HW];              // pix | flags<<14 (sorted by pix)
__device__ __align__(16) float d_cat[(size_t)Bb * 64 * HW];  // CHANNEL-FIRST [b][ch][pix]
__device__ __align__(16) float d_wft[9 * 64 * 32];           // [kl][ch][o]

// ---------------- f32x2 helpers ----------------
__device__ __forceinline__ ull pack2(float v) {
    ull r; asm("mov.b64 %0, {%1, %1};" : "=l"(r) : "f"(v)); return r;
}
__device__ __forceinline__ ull ffma2(ull a, ull b, ull c) {
    ull d; asm("fma.rn.f32x2 %0, %1, %2, %3;" : "=l"(d) : "l"(a), "l"(b), "l"(c)); return d;
}

// ---------------- pool: adaptive 3x3 avg, coalesced column-striped ----------------
// grid = Bb*Cc (512), block = 128. Thread x owns image column x.
__global__ void __launch_bounds__(128) pool_kernel(const float* __restrict__ in) {
    int bc = blockIdx.x;
    int x = threadIdx.x;
    const float* img = in + (size_t)bc * HW;
    float rb0 = 0.f, rb1 = 0.f, rb2 = 0.f;
    #pragma unroll 4
    for (int yy = 0; yy < Hh; yy++) {
        float v = __ldg(img + yy * Ww + x);   // coalesced across threads
        if (yy < 43) rb0 += v;
        if (yy >= 42 && yy < 86) rb1 += v;
        if (yy >= 85) rb2 += v;
    }
    __shared__ float srow[3][128];
    srow[0][x] = rb0; srow[1][x] = rb1; srow[2][x] = rb2;
    __syncthreads();
    if (x < 9) {
        int i = x / 3, j = x % 3;
        const int s[3] = {0, 42, 85}, e[3] = {43, 86, 128};
        const int span[3] = {43, 44, 43};
        float ssum = 0.f;
        for (int xx = s[j]; xx < e[j]; xx++) ssum += srow[i][xx];   // fixed order: deterministic
        d_pool[bc * 9 + x] = ssum / (float)(span[i] * span[j]);
    }
}

// ---------------- gate: sigmoid(w1 @ pooled + b1) ----------------
// grid = Bb, block = 576 (one thread per (rr,kl))
__global__ void __launch_bounds__(576) gate_kernel(
    const float* __restrict__ w1, const float* __restrict__ b1) {
    int b = blockIdx.x, t = threadIdx.x;
    int rr = t / 9, kl = t % 9;
    float s = __ldg(b1 + rr);
    #pragma unroll
    for (int c = 0; c < Cc; c++)
        s += d_pool[(b * Cc + c) * 9 + kl] * __ldg(w1 + rr * Cc + c);
    d_gate[b * 576 + t] = 1.f / (1.f + expf(-s));
}

// ---------------- kern gen: wide, fully parallel ----------------
// 1.18M outputs, grid 4608 x 256.
__global__ void __launch_bounds__(256) kern_kernel(
    const float* __restrict__ w2, const float* __restrict__ b2) {
    int idx = blockIdx.x * 256 + threadIdx.x;
    int oo = idx & 31;
    int ckl = (idx >> 5) % 288;
    int t2 = idx / (288 * 32);
    int r = t2 & 7;
    int b = t2 >> 3;
    int c = ckl / 9, kl = ckl % 9;
    int jj = r * 1024 + oo * 32 + c;
    float v = __ldg(b2 + jj);
    float4 wa = __ldg((const float4*)(w2 + jj * 8));
    float4 wb = __ldg((const float4*)(w2 + jj * 8 + 4));
    const float* gb = d_gate + b * 576 + r * 72 + kl;   // (r*8+i)*9+kl
    v += gb[0]  * wa.x + gb[9]  * wa.y + gb[18] * wa.z + gb[27] * wa.w;
    v += gb[36] * wb.x + gb[45] * wb.y + gb[54] * wb.z + gb[63] * wb.w;
    d_kern[idx] = v;
}

// ---------------- wf transpose: wft[kl][ch][o] ----------------
__global__ void __launch_bounds__(256) wft_kernel(const float* __restrict__ w_f) {
    int idx = blockIdx.x * 256 + threadIdx.x;
    int o = idx & 31, ch = (idx >> 5) & 63, kl = idx >> 11;
    d_wft[idx] = w_f[(o * 64 + ch) * 9 + kl];
}

// ---------------- S1: argmax select + per-segment counts ----------------
__global__ void __launch_bounds__(256) s1_select_kernel(
    const float* __restrict__ guide,
    const float* __restrict__ w_spa, const float* __restrict__ b_spa,
    const float* __restrict__ w_spec, const float* __restrict__ b_spec) {
    int t = threadIdx.x, seg = blockIdx.x, b = blockIdx.y;
    int pix = seg * 256 + t;

    float gv[Cc];
    #pragma unroll
    for (int c = 0; c < Cc; c++)
        gv[c] = __ldg(guide + ((size_t)(b * Cc + c)) * HW + pix);

    float best1 = -1e30f, best2 = -1e30f;
    int r1 = 0, r2 = 0;
    for (int r = 0; r < Rr; r++) {
        float s1 = __ldg(b_spa + r), s2 = __ldg(b_spec + r);
        #pragma unroll
        for (int c = 0; c < Cc; c++) {
            s1 += gv[c] * __ldg(w_spa + r * Cc + c);
            s2 += gv[c] * __ldg(w_spec + r * Cc + c);
        }
        if (s1 > best1) { best1 = s1; r1 = r; }
        if (s2 > best2) { best2 = s2; r2 = r; }
    }
    d_sel[b * HW + pix] = (unsigned char)(r1 | (r2 << 3));

    __shared__ int scnt[Rr];
    if (t < Rr) scnt[t] = 0;
    __syncthreads();
    if (r1 == r2) atomicAdd(&scnt[r1], 1);
    else { atomicAdd(&scnt[r1], 1); atomicAdd(&scnt[r2], 1); }
    __syncthreads();
    if (t < Rr) d_segcnt[(b * Rr + t) * 64 + seg] = scnt[t];
}

// ---------------- S2: per-list exclusive scan over segments ----------------
__global__ void s2_scan_kernel() {
    int t = threadIdx.x;           // one thread per (b,r) list
    if (t >= Bb * Rr) return;
    int s = 0;
    for (int seg = 0; seg < 64; seg++) {
        d_segbase[t * 64 + seg] = s;
        s += d_segcnt[t * 64 + seg];
    }
    d_cnt[t] = s;
}

// ---------------- S3: emit sorted lists (ballot rank, deterministic) ----------------
__global__ void __launch_bounds__(256) s3_emit_kernel() {
    int t = threadIdx.x, seg = blockIdx.x, b = blockIdx.y;
    int w = t >> 5, lane = t & 31;
    int pix = seg * 256 + t;
    int sel = d_sel[b * HW + pix];
    int r1 = sel & 7, r2 = sel >> 3;

    __shared__ int wcnt[8][8];    // [warp][r]
    int rank1 = 0, rank2 = 0;
    unsigned ltm = (1u << lane) - 1u;
    #pragma unroll
    for (int r = 0; r < Rr; r++) {
        unsigned m = __ballot_sync(0xFFFFFFFFu, (r1 == r) || (r2 == r));
        if (lane == 0) wcnt[w][r] = __popc(m);
        if (r1 == r) rank1 = __popc(m & ltm);
        if (r2 == r) rank2 = __popc(m & ltm);
    }
    __syncthreads();
    int wb1 = 0, wb2 = 0;
    for (int w2 = 0; w2 < w; w2++) { wb1 += wcnt[w2][r1]; wb2 += wcnt[w2][r2]; }

    unsigned short pv = (unsigned short)pix;
    if (r1 == r2) {
        int off = d_segbase[(b * Rr + r1) * 64 + seg] + wb1 + rank1;
        d_list[(b * Rr + r1) * HW + off] = (unsigned short)(pv | (3u << 14));
    } else {
        int off1 = d_segbase[(b * Rr + r1) * 64 + seg] + wb1 + rank1;
        d_list[(b * Rr + r1) * HW + off1] = (unsigned short)(pv | (1u << 14));
        int off2 = d_segbase[(b * Rr + r2) * 64 + seg] + wb2 + rank2;
        d_list[(b * Rr + r2) * HW + off2] = (unsigned short)(pv | (2u << 14));
    }
}

// ---------------- dynconv: sorted-list selected-region conv ----------------
// grid (128, 8, 16), block 256. warp = 16 entries (2 streams x 8 lanes) x 32 oo.
__global__ void __launch_bounds__(256) dynconv_kernel(const float* __restrict__ in) {
    int b = blockIdx.z, r = blockIdx.y;
    int cnt = d_cnt[b * Rr + r];
    int base = blockIdx.x * 128;
    if (base >= cnt) return;

    __shared__ __align__(16) float ks[288 * 32];
    {
        const float4* kg = (const float4*)(d_kern + (size_t)(b * Rr + r) * 9216);
        float4* kd = (float4*)ks;
        for (int i = threadIdx.x; i < 2304; i += 256) kd[i] = kg[i];
    }
    __syncthreads();

    int w = threadIdx.x >> 5, lane = threadIdx.x & 31;
    int p = lane & 7, g = lane >> 3;
    const unsigned short* lst = d_list + (b * Rr + r) * HW;
    const float* inb = in + (size_t)b * Cc * HW;

    int e0 = base + w * 16 + p;
    int e1 = e0 + 8;
    int ent0 = (e0 < cnt) ? (int)lst[e0] : -1;
    int ent1 = (e1 < cnt) ? (int)lst[e1] : -1;
    int f0 = (ent0 >= 0) ? (ent0 >> 14) : 0;
    int f1 = (ent1 >= 0) ? (ent1 >> 14) : 0;
    int pix0 = ent0 & 0x3FFF, pix1 = ent1 & 0x3FFF;
    int y0 = pix0 >> 7, x0 = pix0 & 127;
    int y1 = pix1 >> 7, x1 = pix1 & 127;
    bool t0 = y0 > 0, bo0 = y0 < Hh - 1, l0 = x0 > 0, ri0 = x0 < Ww - 1;
    bool t1 = y1 > 0, bo1 = y1 < Hh - 1, l1 = x1 > 0, ri1 = x1 < Ww - 1;

    const float* p0 = inb + (long)(y0 - 1) * Ww + (x0 - 1);
    const float* p1 = inb + (long)(y1 - 1) * Ww + (x1 - 1);

    ull acc0[4] = {0, 0, 0, 0}, acc1[4] = {0, 0, 0, 0};

    for (int c = 0; c < Cc; c++, p0 += HW, p1 += HW) {
        const float* kc = ks + c * 288;   // c*9*32
        #pragma unroll
        for (int tap = 0; tap < 9; tap++) {
            const int ky = tap / 3, kx = tap % 3;
            bool rv0 = (ky == 0) ? t0 : ((ky == 2) ? bo0 : true);
            bool cv0 = (kx == 0) ? l0 : ((kx == 2) ? ri0 : true);
            bool rv1 = (ky == 0) ? t1 : ((ky == 2) ? bo1 : true);
            bool cv1 = (kx == 0) ? l1 : ((kx == 2) ? ri1 : true);
            float v0 = (rv0 && cv0) ? __ldg(p0 + ky * Ww + kx) : 0.f;
            float v1 = (rv1 && cv1) ? __ldg(p1 + ky * Ww + kx) : 0.f;
            ull a0 = pack2(v0), a1 = pack2(v1);
            const ulonglong2* kp = (const ulonglong2*)(kc + tap * 32 + g * 8);
            ulonglong2 ka = kp[0];
            ulonglong2 kb = kp[1];
            acc0[0] = ffma2(a0, ka.x, acc0[0]); acc0[1] = ffma2(a0, ka.y, acc0[1]);
            acc0[2] = ffma2(a0, kb.x, acc0[2]); acc0[3] = ffma2(a0, kb.y, acc0[3]);
            acc1[0] = ffma2(a1, ka.x, acc1[0]); acc1[1] = ffma2(a1, ka.y, acc1[1]);
            acc1[2] = ffma2(a1, kb.x, acc1[2]); acc1[3] = ffma2(a1, kb.y, acc1[3]);
        }
    }

    float* catb = d_cat + (size_t)b * 64 * HW;
    const float* a0f = (const float*)acc0;
    const float* a1f = (const float*)acc1;
    if (f0 & 1) {
        #pragma unroll
        for (int u = 0; u < 8; u++) catb[(g * 8 + u) * HW + pix0] = a0f[u];
    }
    if (f0 & 2) {
        #pragma unroll
        for (int u = 0; u < 8; u++) catb[(32 + g * 8 + u) * HW + pix0] = a0f[u];
    }
    if (f1 & 1) {
        #pragma unroll
        for (int u = 0; u < 8; u++) catb[(g * 8 + u) * HW + pix1] = a1f[u];
    }
    if (f1 & 2) {
        #pragma unroll
        for (int u = 0; u < 8; u++) catb[(32 + g * 8 + u) * HW + pix1] = a1f[u];
    }
}

// ---------------- fusion conv 3x3 (64->32) + bias + residual ----------------
// grid (4, 16, 16), block 256. warp = one row, 32 px (4 streams x 8 lanes) x 32 oo.
__global__ void __launch_bounds__(256) fusion_kernel(
    const float* __restrict__ in, const float* __restrict__ b_f,
    float* __restrict__ out) {
    int t = threadIdx.x, w = t >> 5, lane = t & 31;
    int p = lane & 7, g = lane >> 3;
    int b = blockIdx.z;
    int y = blockIdx.y * 8 + w;
    int xb = blockIdx.x * 32;

    const float* catb = d_cat + (size_t)b * 64 * HW;
    ull acc[4][4];
    #pragma unroll
    for (int j = 0; j < 4; j++)
        #pragma unroll
        for (int u = 0; u < 4; u++) acc[j][u] = 0;

    for (int ch = 0; ch < 64; ch++) {
        const float* chp = catb + (size_t)ch * HW;
        #pragma unroll
        for (int ky = 0; ky < 3; ky++) {
            int yy = y + ky - 1;
            bool rok = ((unsigned)yy < (unsigned)Hh);
            const float* rowp = chp + (long)yy * Ww;
            #pragma unroll
            for (int kx = 0; kx < 3; kx++) {
                const ulonglong2* wp =
                    (const ulonglong2*)(d_wft + (((ky * 3 + kx) * 64 + ch) * 32) + g * 8);
                ulonglong2 ka = __ldg(wp);
                ulonglong2 kb = __ldg(wp + 1);
                #pragma unroll
                for (int j = 0; j < 4; j++) {
                    int xx = xb + j * 8 + p + kx - 1;
                    bool ok = rok && ((unsigned)xx < (unsigned)Ww);
                    float v = ok ? __ldg(rowp + xx) : 0.f;
                    ull a = pack2(v);
                    acc[j][0] = ffma2(a, ka.x, acc[j][0]);
                    acc[j][1] = ffma2(a, ka.y, acc[j][1]);
                    acc[j][2] = ffma2(a, kb.x, acc[j][2]);
                    acc[j][3] = ffma2(a, kb.y, acc[j][3]);
                }
            }
        }
    }

    #pragma unroll
    for (int j = 0; j < 4; j++) {
        int x = xb + j * 8 + p;
        long pixo = (long)y * Ww + x;
        const float* af = (const float*)acc[j];
        #pragma unroll
        for (int u = 0; u < 8; u++) {
            int o = g * 8 + u;
            size_t idx = ((size_t)(b * OUTC + o)) * HW + pixo;
            out[idx] = af[u] + __ldg(b_f + o) + __ldg(in + idx);
        }
    }
}

// ---------------- launch ----------------
extern "C" void kernel_launch(void* const* d_in, const int* in_sizes, int n_in,
                              void* d_out, int out_size) {
    const float* input  = (const float*)d_in[0];
    const float* guide  = (const float*)d_in[1];
    const float* w1     = (const float*)d_in[2];
    const float* b1     = (const float*)d_in[3];
    const float* w2     = (const float*)d_in[4];
    const float* b2     = (const float*)d_in[5];
    const float* w_spa  = (const float*)d_in[6];
    const float* b_spa  = (const float*)d_in[7];
    const float* w_spec = (const float*)d_in[8];
    const float* b_spec = (const float*)d_in[9];
    const float* w_f    = (const float*)d_in[10];
    const float* b_f    = (const float*)d_in[11];
    float* out = (float*)d_out;

    pool_kernel<<<Bb * Cc, 128>>>(input);
    gate_kernel<<<Bb, 576>>>(w1, b1);
    kern_kernel<<<Bb * Rr * 288 * 32 / 256, 256>>>(w2, b2);
    wft_kernel<<<72, 256>>>(w_f);
    s1_select_kernel<<<dim3(64, Bb), 256>>>(guide, w_spa, b_spa, w_spec, b_spec);
    s2_scan_kernel<<<1, 128>>>();
    s3_emit_kernel<<<dim3(64, Bb), 256>>>();
    dynconv_kernel<<<dim3(128, Rr, Bb), 256>>>(input);
    fusion_kernel<<<dim3(4, 16, Bb), 256>>>(input, b_f, out);
}

// round 5
// speedup vs baseline: 2.0115x; 1.3258x over previous
#include <cuda_runtime.h>
#include <math.h>
#include <stdint.h>

#define Bb 16
#define Cc 32
#define Hh 128
#define Ww 128
#define HW 16384
#define Rr 8
#define OUTC 32

typedef unsigned long long ull;

// ---------------- scratch (device globals; no allocation) ----------------
__device__ __align__(16) float d_kern[Bb * Rr * 288 * 32];   // [b][r][c*9+kl][oo]
__device__ float          d_pool[Bb * Cc * 9];               // [b][c][kl]
__device__ float          d_gate[Bb * 576];                  // [b][rr*9+kl]
__device__ __align__(16) float d_int[(size_t)Bb * HW * 32];  // channel-inner input [b][pix][c]
__device__ unsigned char  d_sel[Bb * HW];                    // r1 | r2<<3
__device__ int            d_segcnt[Bb * Rr * 64];
__device__ int            d_segbase[Bb * Rr * 64];
__device__ int            d_cnt[Bb * Rr];
__device__ unsigned short d_list[Bb * Rr * HW];              // pix | flags<<14 (sorted by pix)
__device__ __align__(16) float d_cat[(size_t)Bb * 64 * HW];  // CHANNEL-FIRST [b][ch][pix]
__device__ __align__(16) float d_wft[9 * 64 * 32];           // [kl][ch][o]

// ---------------- f32x2 helpers ----------------
__device__ __forceinline__ ull pack2(float v) {
    ull r; asm("mov.b64 %0, {%1, %1};" : "=l"(r) : "f"(v)); return r;
}
__device__ __forceinline__ ull ffma2(ull a, ull b, ull c) {
    ull d; asm("fma.rn.f32x2 %0, %1, %2, %3;" : "=l"(d) : "l"(a), "l"(b), "l"(c)); return d;
}

// ---------------- pool: adaptive 3x3 avg, coalesced column-striped ----------------
__global__ void __launch_bounds__(128) pool_kernel(const float* __restrict__ in) {
    int bc = blockIdx.x;
    int x = threadIdx.x;
    const float* img = in + (size_t)bc * HW;
    float rb0 = 0.f, rb1 = 0.f, rb2 = 0.f;
    #pragma unroll 4
    for (int yy = 0; yy < Hh; yy++) {
        float v = __ldg(img + yy * Ww + x);
        if (yy < 43) rb0 += v;
        if (yy >= 42 && yy < 86) rb1 += v;
        if (yy >= 85) rb2 += v;
    }
    __shared__ float srow[3][128];
    srow[0][x] = rb0; srow[1][x] = rb1; srow[2][x] = rb2;
    __syncthreads();
    if (x < 9) {
        int i = x / 3, j = x % 3;
        const int s[3] = {0, 42, 85}, e[3] = {43, 86, 128};
        const int span[3] = {43, 44, 43};
        float ssum = 0.f;
        for (int xx = s[j]; xx < e[j]; xx++) ssum += srow[i][xx];
        d_pool[bc * 9 + x] = ssum / (float)(span[i] * span[j]);
    }
}

// ---------------- gate ----------------
__global__ void __launch_bounds__(576) gate_kernel(
    const float* __restrict__ w1, const float* __restrict__ b1) {
    int b = blockIdx.x, t = threadIdx.x;
    int rr = t / 9, kl = t % 9;
    float s = __ldg(b1 + rr);
    #pragma unroll
    for (int c = 0; c < Cc; c++)
        s += d_pool[(b * Cc + c) * 9 + kl] * __ldg(w1 + rr * Cc + c);
    d_gate[b * 576 + t] = 1.f / (1.f + expf(-s));
}

// ---------------- kern gen ----------------
__global__ void __launch_bounds__(256) kern_kernel(
    const float* __restrict__ w2, const float* __restrict__ b2) {
    int idx = blockIdx.x * 256 + threadIdx.x;
    int oo = idx & 31;
    int ckl = (idx >> 5) % 288;
    int t2 = idx / (288 * 32);
    int r = t2 & 7;
    int b = t2 >> 3;
    int c = ckl / 9, kl = ckl % 9;
    int jj = r * 1024 + oo * 32 + c;
    float v = __ldg(b2 + jj);
    float4 wa = __ldg((const float4*)(w2 + jj * 8));
    float4 wb = __ldg((const float4*)(w2 + jj * 8 + 4));
    const float* gb = d_gate + b * 576 + r * 72 + kl;
    v += gb[0]  * wa.x + gb[9]  * wa.y + gb[18] * wa.z + gb[27] * wa.w;
    v += gb[36] * wb.x + gb[45] * wb.y + gb[54] * wb.z + gb[63] * wb.w;
    d_kern[idx] = v;
}

// ---------------- wf transpose: wft[kl][ch][o] ----------------
__global__ void __launch_bounds__(256) wft_kernel(const float* __restrict__ w_f) {
    int idx = blockIdx.x * 256 + threadIdx.x;
    int o = idx & 31, ch = (idx >> 5) & 63, kl = idx >> 11;
    d_wft[idx] = w_f[(o * 64 + ch) * 9 + kl];
}

// ---------------- input transpose: d_int[b][pix][c] ----------------
__global__ void __launch_bounds__(256) transpose_kernel(const float* __restrict__ in) {
    __shared__ float t[32][33];
    int px0 = blockIdx.x * 32, b = blockIdx.y;
    int lane = threadIdx.x & 31, wr = threadIdx.x >> 5;
    #pragma unroll
    for (int i = 0; i < 4; i++) {
        int c = wr + i * 8;
        t[c][lane] = __ldg(in + ((size_t)(b * Cc + c)) * HW + px0 + lane);
    }
    __syncthreads();
    #pragma unroll
    for (int i = 0; i < 4; i++) {
        int pr = wr + i * 8;
        d_int[((size_t)b * HW + px0 + pr) * 32 + lane] = t[lane][pr];
    }
}

// ---------------- S1: argmax select + per-segment counts ----------------
__global__ void __launch_bounds__(256) s1_select_kernel(
    const float* __restrict__ guide,
    const float* __restrict__ w_spa, const float* __restrict__ b_spa,
    const float* __restrict__ w_spec, const float* __restrict__ b_spec) {
    int t = threadIdx.x, seg = blockIdx.x, b = blockIdx.y;
    int pix = seg * 256 + t;

    float gv[Cc];
    #pragma unroll
    for (int c = 0; c < Cc; c++)
        gv[c] = __ldg(guide + ((size_t)(b * Cc + c)) * HW + pix);

    float best1 = -1e30f, best2 = -1e30f;
    int r1 = 0, r2 = 0;
    for (int r = 0; r < Rr; r++) {
        float s1 = __ldg(b_spa + r), s2 = __ldg(b_spec + r);
        #pragma unroll
        for (int c = 0; c < Cc; c++) {
            s1 += gv[c] * __ldg(w_spa + r * Cc + c);
            s2 += gv[c] * __ldg(w_spec + r * Cc + c);
        }
        if (s1 > best1) { best1 = s1; r1 = r; }
        if (s2 > best2) { best2 = s2; r2 = r; }
    }
    d_sel[b * HW + pix] = (unsigned char)(r1 | (r2 << 3));

    __shared__ int scnt[Rr];
    if (t < Rr) scnt[t] = 0;
    __syncthreads();
    if (r1 == r2) atomicAdd(&scnt[r1], 1);
    else { atomicAdd(&scnt[r1], 1); atomicAdd(&scnt[r2], 1); }
    __syncthreads();
    if (t < Rr) d_segcnt[(b * Rr + t) * 64 + seg] = scnt[t];
}

// ---------------- S2: per-list exclusive scan over segments ----------------
__global__ void s2_scan_kernel() {
    int t = threadIdx.x;
    if (t >= Bb * Rr) return;
    int s = 0;
    for (int seg = 0; seg < 64; seg++) {
        d_segbase[t * 64 + seg] = s;
        s += d_segcnt[t * 64 + seg];
    }
    d_cnt[t] = s;
}

// ---------------- S3: emit sorted lists ----------------
__global__ void __launch_bounds__(256) s3_emit_kernel() {
    int t = threadIdx.x, seg = blockIdx.x, b = blockIdx.y;
    int w = t >> 5, lane = t & 31;
    int pix = seg * 256 + t;
    int sel = d_sel[b * HW + pix];
    int r1 = sel & 7, r2 = sel >> 3;

    __shared__ int wcnt[8][8];
    int rank1 = 0, rank2 = 0;
    unsigned ltm = (1u << lane) - 1u;
    #pragma unroll
    for (int r = 0; r < Rr; r++) {
        unsigned m = __ballot_sync(0xFFFFFFFFu, (r1 == r) || (r2 == r));
        if (lane == 0) wcnt[w][r] = __popc(m);
        if (r1 == r) rank1 = __popc(m & ltm);
        if (r2 == r) rank2 = __popc(m & ltm);
    }
    __syncthreads();
    int wb1 = 0, wb2 = 0;
    for (int w2 = 0; w2 < w; w2++) { wb1 += wcnt[w2][r1]; wb2 += wcnt[w2][r2]; }

    unsigned short pv = (unsigned short)pix;
    if (r1 == r2) {
        int off = d_segbase[(b * Rr + r1) * 64 + seg] + wb1 + rank1;
        d_list[(b * Rr + r1) * HW + off] = (unsigned short)(pv | (3u << 14));
    } else {
        int off1 = d_segbase[(b * Rr + r1) * 64 + seg] + wb1 + rank1;
        d_list[(b * Rr + r1) * HW + off1] = (unsigned short)(pv | (1u << 14));
        int off2 = d_segbase[(b * Rr + r2) * 64 + seg] + wb2 + rank2;
        d_list[(b * Rr + r2) * HW + off2] = (unsigned short)(pv | (2u << 14));
    }
}

// ---------------- dynconv v2: channel-inner gathers, 2 streams x 16 px x 2 oo-halves ----------------
// grid (128, 8, 16), block 256 (8 warps). Block covers 256 sorted entries.
__global__ void __launch_bounds__(256) dynconv_kernel() {
    int b = blockIdx.z, r = blockIdx.y;
    int cnt = d_cnt[b * Rr + r];
    int base = blockIdx.x * 256;
    if (base >= cnt) return;

    __shared__ __align__(16) float ks[288 * 32];   // [c*9+tap][oo]
    {
        const float4* kg = (const float4*)(d_kern + (size_t)(b * Rr + r) * 9216);
        float4* kd = (float4*)ks;
        #pragma unroll
        for (int i = 0; i < 9; i++) kd[threadIdx.x + 256 * i] = kg[threadIdx.x + 256 * i];
    }
    __syncthreads();

    int w = threadIdx.x >> 5, lane = threadIdx.x & 31;
    int p = lane & 15, gg = lane >> 4;     // gg selects oo half (16 oo)
    const unsigned short* lst = d_list + (b * Rr + r) * HW;
    const float* inb = d_int + (size_t)b * HW * 32;

    int e0 = base + w * 32 + p;
    int e1 = e0 + 16;
    int ent0 = (e0 < cnt) ? (int)lst[e0] : 0;
    int ent1 = (e1 < cnt) ? (int)lst[e1] : 0;
    int f0 = (e0 < cnt) ? (ent0 >> 14) : 0;
    int f1 = (e1 < cnt) ? (ent1 >> 14) : 0;
    int pix0 = ent0 & 0x3FFF, pix1 = ent1 & 0x3FFF;
    int y0 = pix0 >> 7, x0 = pix0 & 127;
    int y1 = pix1 >> 7, x1 = pix1 & 127;

    unsigned vm0 = 0, vm1 = 0;
    #pragma unroll
    for (int tap = 0; tap < 9; tap++) {
        int ky = tap / 3, kx = tap % 3;
        int ya = y0 + ky - 1, xa = x0 + kx - 1;
        int yb = y1 + ky - 1, xb = x1 + kx - 1;
        if ((unsigned)ya < 128u && (unsigned)xa < 128u) vm0 |= 1u << tap;
        if ((unsigned)yb < 128u && (unsigned)xb < 128u) vm1 |= 1u << tap;
    }
    const float* p0 = inb + ((long)(y0 - 1) * Ww + (x0 - 1)) * 32;
    const float* p1 = inb + ((long)(y1 - 1) * Ww + (x1 - 1)) * 32;

    ull acc0[8], acc1[8];
    #pragma unroll
    for (int u = 0; u < 8; u++) { acc0[u] = 0; acc1[u] = 0; }

    const float4 z4 = make_float4(0.f, 0.f, 0.f, 0.f);
    for (int cq = 0; cq < 8; cq++) {
        const float* kq = ks + cq * 4 * 288 + gg * 16;   // c stride = 9*32 = 288 floats
        #pragma unroll
        for (int tap = 0; tap < 9; tap++) {
            const int ky = tap / 3, kx = tap % 3;
            const int off = (ky * Ww + kx) * 32 + cq * 4;
            float4 v0 = (vm0 >> tap & 1) ? __ldg((const float4*)(p0 + off)) : z4;
            float4 v1 = (vm1 >> tap & 1) ? __ldg((const float4*)(p1 + off)) : z4;
            #pragma unroll
            for (int ci = 0; ci < 4; ci++) {
                const ulonglong2* wp = (const ulonglong2*)(kq + ci * 288 + tap * 32);
                ulonglong2 wA = wp[0], wB = wp[1], wC = wp[2], wD = wp[3];
                float vc0 = (ci == 0) ? v0.x : (ci == 1) ? v0.y : (ci == 2) ? v0.z : v0.w;
                float vc1 = (ci == 0) ? v1.x : (ci == 1) ? v1.y : (ci == 2) ? v1.z : v1.w;
                ull a0 = pack2(vc0), a1 = pack2(vc1);
                acc0[0] = ffma2(a0, wA.x, acc0[0]); acc0[1] = ffma2(a0, wA.y, acc0[1]);
                acc0[2] = ffma2(a0, wB.x, acc0[2]); acc0[3] = ffma2(a0, wB.y, acc0[3]);
                acc0[4] = ffma2(a0, wC.x, acc0[4]); acc0[5] = ffma2(a0, wC.y, acc0[5]);
                acc0[6] = ffma2(a0, wD.x, acc0[6]); acc0[7] = ffma2(a0, wD.y, acc0[7]);
                acc1[0] = ffma2(a1, wA.x, acc1[0]); acc1[1] = ffma2(a1, wA.y, acc1[1]);
                acc1[2] = ffma2(a1, wB.x, acc1[2]); acc1[3] = ffma2(a1, wB.y, acc1[3]);
                acc1[4] = ffma2(a1, wC.x, acc1[4]); acc1[5] = ffma2(a1, wC.y, acc1[5]);
                acc1[6] = ffma2(a1, wD.x, acc1[6]); acc1[7] = ffma2(a1, wD.y, acc1[7]);
            }
        }
    }

    float* catb = d_cat + (size_t)b * 64 * HW;
    const float* a0f = (const float*)acc0;
    const float* a1f = (const float*)acc1;
    int ob = gg * 16;
    if (f0 & 1) {
        #pragma unroll
        for (int u = 0; u < 16; u++) catb[(ob + u) * HW + pix0] = a0f[u];
    }
    if (f0 & 2) {
        #pragma unroll
        for (int u = 0; u < 16; u++) catb[(32 + ob + u) * HW + pix0] = a0f[u];
    }
    if (f1 & 1) {
        #pragma unroll
        for (int u = 0; u < 16; u++) catb[(ob + u) * HW + pix1] = a1f[u];
    }
    if (f1 & 2) {
        #pragma unroll
        for (int u = 0; u < 16; u++) catb[(32 + ob + u) * HW + pix1] = a1f[u];
    }
}

// ---------------- fusion v2: lane=pixel, all 32 oo per lane, weights in smem ----------------
// grid (1, 32, 16), block 256 (8 warps = 4 rows x 2 half-rows). Dynamic smem 73728 B.
__global__ void __launch_bounds__(256) fusion_kernel(
    const float* __restrict__ in, const float* __restrict__ b_f,
    float* __restrict__ out) {
    extern __shared__ __align__(16) float ws[];   // [tap][ch][oo] = 18432 floats
    {
        const float4* wsrc = (const float4*)d_wft;
        float4* wdst = (float4*)ws;
        #pragma unroll
        for (int i = 0; i < 18; i++) wdst[threadIdx.x + 256 * i] = wsrc[threadIdx.x + 256 * i];
    }
    __syncthreads();

    int w = threadIdx.x >> 5, lane = threadIdx.x & 31;
    int b = blockIdx.z;
    int y = blockIdx.y * 4 + (w >> 1);
    int xh = (w & 1) * 64;
    int xa = xh + lane, xb2 = xh + 32 + lane;

    const float* catb = d_cat + (size_t)b * 64 * HW;

    ull acc0[16], acc1[16];
    #pragma unroll
    for (int u = 0; u < 16; u++) { acc0[u] = 0; acc1[u] = 0; }

    for (int ch = 0; ch < 64; ch++) {
        const float* chp = catb + (size_t)ch * HW;
        #pragma unroll
        for (int tap = 0; tap < 9; tap++) {
            const int ky = tap / 3, kx = tap % 3;
            int yy = y + ky - 1;
            bool rok = (unsigned)yy < (unsigned)Hh;
            const float* rowp = chp + yy * Ww;
            int xx0 = xa + kx - 1, xx1 = xb2 + kx - 1;
            float v0 = (rok && (unsigned)xx0 < (unsigned)Ww) ? __ldg(rowp + xx0) : 0.f;
            float v1 = (rok && (unsigned)xx1 < (unsigned)Ww) ? __ldg(rowp + xx1) : 0.f;
            ull a0 = pack2(v0), a1 = pack2(v1);
            const ulonglong2* wp = (const ulonglong2*)(ws + (tap * 64 + ch) * 32);
            #pragma unroll
            for (int q = 0; q < 8; q++) {
                ulonglong2 wq = wp[q];
                acc0[q * 2]     = ffma2(a0, wq.x, acc0[q * 2]);
                acc0[q * 2 + 1] = ffma2(a0, wq.y, acc0[q * 2 + 1]);
                acc1[q * 2]     = ffma2(a1, wq.x, acc1[q * 2]);
                acc1[q * 2 + 1] = ffma2(a1, wq.y, acc1[q * 2 + 1]);
            }
        }
    }

    const float* a0f = (const float*)acc0;
    const float* a1f = (const float*)acc1;
    long pix0 = (long)y * Ww + xa;
    long pix1 = (long)y * Ww + xb2;
    #pragma unroll
    for (int o = 0; o < 32; o++) {
        float bias = __ldg(b_f + o);
        size_t idx0 = ((size_t)(b * OUTC + o)) * HW + pix0;
        size_t idx1 = ((size_t)(b * OUTC + o)) * HW + pix1;
        out[idx0] = a0f[o] + bias + __ldg(in + idx0);
        out[idx1] = a1f[o] + bias + __ldg(in + idx1);
    }
}

// ---------------- launch ----------------
extern "C" void kernel_launch(void* const* d_in, const int* in_sizes, int n_in,
                              void* d_out, int out_size) {
    const float* input  = (const float*)d_in[0];
    const float* guide  = (const float*)d_in[1];
    const float* w1     = (const float*)d_in[2];
    const float* b1     = (const float*)d_in[3];
    const float* w2     = (const float*)d_in[4];
    const float* b2     = (const float*)d_in[5];
    const float* w_spa  = (const float*)d_in[6];
    const float* b_spa  = (const float*)d_in[7];
    const float* w_spec = (const float*)d_in[8];
    const float* b_spec = (const float*)d_in[9];
    const float* w_f    = (const float*)d_in[10];
    const float* b_f    = (const float*)d_in[11];
    float* out = (float*)d_out;

    cudaFuncSetAttribute(fusion_kernel, cudaFuncAttributeMaxDynamicSharedMemorySize, 73728);

    pool_kernel<<<Bb * Cc, 128>>>(input);
    gate_kernel<<<Bb, 576>>>(w1, b1);
    kern_kernel<<<Bb * Rr * 288 * 32 / 256, 256>>>(w2, b2);
    wft_kernel<<<72, 256>>>(w_f);
    transpose_kernel<<<dim3(HW / 32, Bb), 256>>>(input);
    s1_select_kernel<<<dim3(64, Bb), 256>>>(guide, w_spa, b_spa, w_spec, b_spec);
    s2_scan_kernel<<<1, 128>>>();
    s3_emit_kernel<<<dim3(64, Bb), 256>>>();
    dynconv_kernel<<<dim3(128, Rr, Bb), 256>>>();
    fusion_kernel<<<dim3(1, 32, Bb), 256, 73728>>>(input, b_f, out);
}